// round 12
// baseline (speedup 1.0000x reference)
#include <cuda_runtime.h>
#include <cstdint>

#define BB 16
#define QL 32
#define TN 10
#define AL 10
#define EE 300
#define HH 256
#define NJOB (BB * TN)
#define NEGV -10000000000.0f

// strides
#define RS 12     // encT row stride (floats): 48B rows
#define QP 308    // q_emb smem row stride
#define AP 304    // aw3 smem row stride

// ---- shared memory layout (floats) ----
#define OFF_W     0                 // w1,w2,w3 : 900
#define OFF_QE    900               // q_emb [32][308] = 9856 ; reused as GEMM partials
#define OFF_AW3   10756             // aw3 [10][304] = 3040
#define OFF_ENCT  13796             // encT [600][12] = 7200  (byte 55184, 16B aligned)
#define OFF_ATT   20996             // 320
#define OFF_ATTS  21316             // 320
#define OFF_QW2   21636             // 32
#define OFF_QM    21668             // 32
#define OFF_AW1   21700             // 16
#define OFF_AM    21716             // 16
#define OFF_RED   21732             // 8
#define OFF_FLAG  21740             // 1
#define SMEM_FLOATS 21744
#define SMEM_BYTES (SMEM_FLOATS * 4)

__device__ float    g_max_atten[NJOB * QL];
__device__ float    g_score[NJOB];
__device__ unsigned g_done = 0;

__device__ __forceinline__ void fma_f32x2(unsigned long long& acc,
                                          unsigned long long a,
                                          unsigned long long b)
{
    asm("fma.rn.f32x2 %0, %1, %2, %0;" : "+l"(acc) : "l"(a), "l"(b));
}

__device__ __forceinline__ unsigned long long pack2(float v)
{
    unsigned long long r;
    uint32_t u = __float_as_uint(v);
    asm("mov.b64 %0, {%1, %1};" : "=l"(r) : "r"(u));
    return r;
}

__global__ void __launch_bounds__(512, 2)
topic_fused(const int* __restrict__ q, const int* __restrict__ alia,
            const float* __restrict__ els, const float* __restrict__ elo,
            const float* __restrict__ cate, const float* __restrict__ emb,
            const float* __restrict__ sim_w, const float* __restrict__ sim_b,
            const float* __restrict__ enc_w, const float* __restrict__ enc_b,
            const float* __restrict__ qlin_w, const float* __restrict__ qlin_b,
            const float* __restrict__ cls_w, const float* __restrict__ cls_b,
            float* __restrict__ out)
{
    extern __shared__ float sm[];
    float* w1      = sm + OFF_W;
    float* w2      = w1 + EE;
    float* w3      = w2 + EE;
    float* q_emb   = sm + OFF_QE;
    float* aw3     = sm + OFF_AW3;
    float* encT    = sm + OFF_ENCT;
    float* atten   = sm + OFF_ATT;
    float* attensm = sm + OFF_ATTS;
    float* qW2     = sm + OFF_QW2;
    float* qmaskS  = sm + OFF_QM;
    float* aW1     = sm + OFF_AW1;
    float* amaskS  = sm + OFF_AM;
    float* red     = sm + OFF_RED;

    const int tid  = threadIdx.x;
    const int lane = tid & 31;
    const int wid  = tid >> 5;
    const int job  = blockIdx.x;
    const int b    = job / TN;

    const float simb = sim_b[0];

    for (int i = tid; i < 3 * EE; i += 512) sm[OFF_W + i] = sim_w[i];
    __syncthreads();

    // ---- q rows: 16 warps x 2 rows, float4 gather ----
    for (int j = wid; j < QL; j += 16) {
        int idx = q[b * QL + j];
        const float4* er = reinterpret_cast<const float4*>(emb + (size_t)idx * EE);
        float4 xv[3];
        float ss = 0.f;
        #pragma unroll
        for (int k = 0; k < 3; k++) {
            int f4 = lane + 32 * k;
            if (f4 < 75) {
                float4 v = er[f4];
                xv[k] = v;
                ss += v.x * v.x + v.y * v.y + v.z * v.z + v.w * v.w;
            }
        }
        #pragma unroll
        for (int o = 16; o; o >>= 1) ss += __shfl_xor_sync(0xffffffffu, ss, o);
        float scale = (idx == 0) ? 0.f : 1.f / fmaxf(sqrtf(ss), 1e-12f);
        float dot = 0.f;
        #pragma unroll
        for (int k = 0; k < 3; k++) {
            int f4 = lane + 32 * k;
            if (f4 < 75) {
                float4 v;
                v.x = xv[k].x * scale; v.y = xv[k].y * scale;
                v.z = xv[k].z * scale; v.w = xv[k].w * scale;
                *reinterpret_cast<float4*>(q_emb + j * QP + 4 * f4) = v;
                float4 w = *reinterpret_cast<const float4*>(w2 + 4 * f4);
                dot += v.x * w.x + v.y * w.y + v.z * w.z + v.w * w.w;
            }
        }
        #pragma unroll
        for (int o = 16; o; o >>= 1) dot += __shfl_xor_sync(0xffffffffu, dot, o);
        if (lane == 0) {
            qW2[j]    = dot;
            qmaskS[j] = (idx != 0) ? 1.f : 0.f;
        }
    }

    // ---- alias rows: warps 0..9, float4 gather ----
    if (wid < AL) {
        int a = wid;
        int idx = alia[job * AL + a];
        const float4* er = reinterpret_cast<const float4*>(emb + (size_t)idx * EE);
        float4 xv[3];
        float ss = 0.f;
        #pragma unroll
        for (int k = 0; k < 3; k++) {
            int f4 = lane + 32 * k;
            if (f4 < 75) {
                float4 v = er[f4];
                xv[k] = v;
                ss += v.x * v.x + v.y * v.y + v.z * v.z + v.w * v.w;
            }
        }
        #pragma unroll
        for (int o = 16; o; o >>= 1) ss += __shfl_xor_sync(0xffffffffu, ss, o);
        float scale = (idx == 0) ? 0.f : 1.f / fmaxf(sqrtf(ss), 1e-12f);
        float dot = 0.f;
        #pragma unroll
        for (int k = 0; k < 3; k++) {
            int f4 = lane + 32 * k;
            if (f4 < 75) {
                float4 v;
                v.x = xv[k].x * scale; v.y = xv[k].y * scale;
                v.z = xv[k].z * scale; v.w = xv[k].w * scale;
                int e = 4 * f4;
                float4 w3v = *reinterpret_cast<const float4*>(w3 + e);
                float4 aw;
                aw.x = v.x * w3v.x; aw.y = v.y * w3v.y;
                aw.z = v.z * w3v.z; aw.w = v.w * w3v.w;
                *reinterpret_cast<float4*>(aw3 + a * AP + e) = aw;
                encT[(300 + e + 0) * RS + a] = v.x;
                encT[(300 + e + 1) * RS + a] = v.y;
                encT[(300 + e + 2) * RS + a] = v.z;
                encT[(300 + e + 3) * RS + a] = v.w;
                float4 w1v = *reinterpret_cast<const float4*>(w1 + e);
                dot += v.x * w1v.x + v.y * w1v.y + v.z * w1v.z + v.w * w1v.w;
            }
        }
        #pragma unroll
        for (int o = 16; o; o >>= 1) dot += __shfl_xor_sync(0xffffffffu, dot, o);
        if (lane == 0) {
            aW1[a]    = dot;
            amaskS[a] = (idx != 0) ? 1.f : 0.f;
        }
    }
    __syncthreads();

    // ---- fused attention + softmax: warp = a, lane = q ----
    if (wid < AL) {
        int a = wid, qi = lane;
        const float4* qe = reinterpret_cast<const float4*>(q_emb + qi * QP);
        const float4* ar = reinterpret_cast<const float4*>(aw3 + a * AP);
        float d = 0.f;
        #pragma unroll 5
        for (int c = 0; c < 75; c++) {
            float4 qv = qe[c];
            float4 av = ar[c];
            d += av.x * qv.x + av.y * qv.y + av.z * qv.z + av.w * qv.w;
        }
        float val = aW1[a] + qW2[qi] + d + simb;
        float m = amaskS[a] * qmaskS[qi];
        val = m * val + (1.f - m) * NEGV;
        atten[a * QL + qi] = val;
        float mx = val;
        #pragma unroll
        for (int o = 16; o; o >>= 1) mx = fmaxf(mx, __shfl_xor_sync(0xffffffffu, mx, o));
        float ex = expf(val - mx);
        float s = ex;
        #pragma unroll
        for (int o = 16; o; o >>= 1) s += __shfl_xor_sync(0xffffffffu, s, o);
        attensm[a * QL + qi] = ex / s;
    }
    __syncthreads();

    // ---- cross-a max (warp 10) runs concurrently with alig ----
    if (wid == 10) {
        float mx = atten[lane];
        #pragma unroll
        for (int a = 1; a < AL; a++) mx = fmaxf(mx, atten[a * QL + lane]);
        g_max_atten[job * QL + lane] = mx;
    }

    // ---- alig -> encT rows 0..299 (float4 over e) ----
    for (int p = tid; p < AL * 75; p += 512) {
        int a = p / 75, c = p - a * 75;
        const float* as = attensm + a * QL;
        float4 acc = make_float4(0.f, 0.f, 0.f, 0.f);
        #pragma unroll
        for (int qi = 0; qi < QL; qi++) {
            float s = as[qi];
            float4 qv = *reinterpret_cast<const float4*>(q_emb + qi * QP + c * 4);
            acc.x += s * qv.x; acc.y += s * qv.y; acc.z += s * qv.z; acc.w += s * qv.w;
        }
        int e = c * 4;
        encT[(e + 0) * RS + a] = acc.x;
        encT[(e + 1) * RS + a] = acc.y;
        encT[(e + 2) * RS + a] = acc.z;
        encT[(e + 3) * RS + a] = acc.w;
    }
    __syncthreads();

    // ---- enc GEMM: 128 h-pairs x 4 e-quarters, batched weight prefetch (MLP 6) ----
    {
        const int pr  = tid & 127;         // h-pair index: h0=2p, h1=2p+1
        const int qtr = tid >> 7;          // e-quarter 0..3
        const int e0  = qtr * 150;
        const float2* W2 = reinterpret_cast<const float2*>(enc_w) + pr;

        unsigned long long A01 = 0ull, A23 = 0ull, A45 = 0ull, A67 = 0ull, A89 = 0ull;
        unsigned long long B01 = 0ull, B23 = 0ull, B45 = 0ull, B67 = 0ull, B89 = 0ull;

        #pragma unroll 1
        for (int eb = e0; eb < e0 + 150; eb += 6) {   // 150 = 25 * 6
            float2 wv[6];
            #pragma unroll
            for (int k = 0; k < 6; k++)
                wv[k] = __ldg(W2 + (size_t)(eb + k) * (HH / 2));

            #pragma unroll
            for (int k = 0; k < 6; k++) {
                unsigned long long wp0 = pack2(wv[k].x);
                unsigned long long wp1 = pack2(wv[k].y);

                const float* row = encT + (eb + k) * RS;
                ulonglong2 p0 = *reinterpret_cast<const ulonglong2*>(row);
                ulonglong2 p1 = *reinterpret_cast<const ulonglong2*>(row + 4);
                unsigned long long p2 =
                    *reinterpret_cast<const unsigned long long*>(row + 8);

                fma_f32x2(A01, p0.x, wp0);
                fma_f32x2(A23, p0.y, wp0);
                fma_f32x2(A45, p1.x, wp0);
                fma_f32x2(A67, p1.y, wp0);
                fma_f32x2(A89, p2,   wp0);

                fma_f32x2(B01, p0.x, wp1);
                fma_f32x2(B23, p0.y, wp1);
                fma_f32x2(B45, p1.x, wp1);
                fma_f32x2(B67, p1.y, wp1);
                fma_f32x2(B89, p2,   wp1);
            }
        }

        __syncthreads();   // q_emb region now dead -> reuse as partials
        unsigned long long* partial = reinterpret_cast<unsigned long long*>(q_emb);
        if (qtr != 0) {
            unsigned long long* dst = partial + ((size_t)(qtr - 1) * 128 + pr) * 10;
            dst[0] = A01; dst[1] = A23; dst[2] = A45; dst[3] = A67; dst[4] = A89;
            dst[5] = B01; dst[6] = B23; dst[7] = B45; dst[8] = B67; dst[9] = B89;
        }
        __syncthreads();

        if (qtr == 0) {                     // tid 0..127 = warps 0..3
            unsigned long long C[10] = {A01, A23, A45, A67, A89,
                                        B01, B23, B45, B67, B89};
            #pragma unroll
            for (int qq = 0; qq < 3; qq++) {
                const unsigned long long* src = partial + ((size_t)qq * 128 + pr) * 10;
                #pragma unroll
                for (int k = 0; k < 10; k++) {
                    unsigned long long v = src[k];
                    float lo = __uint_as_float((uint32_t)C[k]) + __uint_as_float((uint32_t)v);
                    float hi = __uint_as_float((uint32_t)(C[k] >> 32)) + __uint_as_float((uint32_t)(v >> 32));
                    C[k] = ((unsigned long long)__float_as_uint(hi) << 32) | __float_as_uint(lo);
                }
            }
            float2 eb = *reinterpret_cast<const float2*>(enc_b + 2 * pr);
            float2 qw = *reinterpret_cast<const float2*>(qlin_w + 2 * pr);
            float s0 = 0.f, s1 = 0.f;
            #pragma unroll
            for (int k = 0; k < 5; k++) {
                s0 += fmaxf(__uint_as_float((uint32_t)C[k]) + eb.x, 0.f);
                s0 += fmaxf(__uint_as_float((uint32_t)(C[k] >> 32)) + eb.x, 0.f);
                s1 += fmaxf(__uint_as_float((uint32_t)C[5 + k]) + eb.y, 0.f);
                s1 += fmaxf(__uint_as_float((uint32_t)(C[5 + k] >> 32)) + eb.y, 0.f);
            }
            float val = s0 * qw.x + s1 * qw.y;
            #pragma unroll
            for (int o = 16; o; o >>= 1) val += __shfl_xor_sync(0xffffffffu, val, o);
            if (lane == 0) red[wid] = val;
        }
        __syncthreads();
        if (tid == 0) {
            g_score[job] = red[0] + red[1] + red[2] + red[3];
        }
    }

    // ---- finisher-block pattern: last arriving block computes the finale ----
    __syncthreads();
    if (tid == 0) {
        __threadfence();
        unsigned old = atomicAdd(&g_done, 1u);
        sm[OFF_FLAG] = (old == NJOB - 1) ? 1.f : 0.f;
    }
    __syncthreads();
    if (sm[OFF_FLAG] != 0.f) {
        __threadfence();           // acquire: other blocks' g_score/g_max_atten visible
        if (tid == 0) g_done = 0;  // reset for next graph replay

        int fb = wid;              // warp per batch, 16 warps
        float c0w = cls_w[0], c1w = cls_w[1], c2w = cls_w[2],
              c3w = cls_w[3], c4w = cls_w[4];
        float cb = cls_b[0];
        float qb = qlin_b[0];

        float ml[TN];
        #pragma unroll
        for (int t = 0; t < TN; t++) {
            float eo = elo[fb * TN + t];
            float es = els[fb * TN + t];
            float ca = cate[(fb * TN + t) * 2 + 0];
            float cbv = cate[(fb * TN + t) * 2 + 1];
            float as = g_score[fb * TN + t] + qb;
            float lg = eo * c0w + es * c1w + ca * c2w + cbv * c3w + as * c4w + cb;
            float tm = ((es + eo) != 0.f) ? 1.f : 0.f;
            ml[t] = tm * lg + (1.f - tm) * NEGV;
        }
        if (lane < TN) out[fb * TN + lane] = ml[lane];

        float mx = ml[0];
        #pragma unroll
        for (int t = 1; t < TN; t++) mx = fmaxf(mx, ml[t]);
        float p[TN];
        float sum = 0.f;
        #pragma unroll
        for (int t = 0; t < TN; t++) { p[t] = expf(ml[t] - mx); sum += p[t]; }
        float inv = 1.f / sum;

        float s = 0.f;
        #pragma unroll
        for (int t = 0; t < TN; t++)
            s += p[t] * inv * g_max_atten[(fb * TN + t) * QL + lane];

        float m2 = s;
        #pragma unroll
        for (int o = 16; o; o >>= 1) m2 = fmaxf(m2, __shfl_xor_sync(0xffffffffu, m2, o));
        float ex = expf(s - m2);
        float tot = ex;
        #pragma unroll
        for (int o = 16; o; o >>= 1) tot += __shfl_xor_sync(0xffffffffu, tot, o);
        out[BB * TN + fb * QL + lane] = ex / tot;
    }
}

extern "C" void kernel_launch(void* const* d_in, const int* in_sizes, int n_in,
                              void* d_out, int out_size)
{
    const int*   q      = (const int*)  d_in[0];
    const int*   alia   = (const int*)  d_in[1];
    const float* els    = (const float*)d_in[2];
    const float* elo    = (const float*)d_in[3];
    const float* cate   = (const float*)d_in[4];
    const float* emb    = (const float*)d_in[5];
    const float* sim_w  = (const float*)d_in[6];
    const float* sim_b  = (const float*)d_in[7];
    const float* enc_w  = (const float*)d_in[8];
    const float* enc_b  = (const float*)d_in[9];
    const float* qlin_w = (const float*)d_in[10];
    const float* qlin_b = (const float*)d_in[11];
    const float* cls_w  = (const float*)d_in[12];
    const float* cls_b  = (const float*)d_in[13];
    float* out = (float*)d_out;

    cudaFuncSetAttribute(topic_fused, cudaFuncAttributeMaxDynamicSharedMemorySize, SMEM_BYTES);

    topic_fused<<<NJOB, 512, SMEM_BYTES>>>(q, alia, els, elo, cate, emb,
                                           sim_w, sim_b, enc_w, enc_b,
                                           qlin_w, qlin_b, cls_w, cls_b, out);
}

// round 13
// speedup vs baseline: 1.0639x; 1.0639x over previous
#include <cuda_runtime.h>
#include <cstdint>

#define BB 16
#define QL 32
#define TN 10
#define AL 10
#define EE 300
#define HH 256
#define NJOB (BB * TN)
#define NEGV -10000000000.0f

// strides
#define RS 12     // encT row stride (floats): 48B rows
#define QP 308    // q_emb smem row stride
#define AP 304    // aw3 smem row stride

// ---- shared memory layout (floats) ----
#define OFF_W     0                 // w1,w2,w3 : 900
#define OFF_QE    900               // q_emb [32][308] = 9856 ; reused as GEMM partials
#define OFF_AW3   10756             // aw3 [10][304] = 3040
#define OFF_ENCT  13796             // encT [600][12] = 7200  (byte 55184, 16B aligned)
#define OFF_ATT   20996             // 320
#define OFF_ATTS  21316             // 320
#define OFF_QW2   21636             // 32
#define OFF_QM    21668             // 32
#define OFF_AW1   21700             // 16
#define OFF_AM    21716             // 16
#define OFF_RED   21732             // 8
#define OFF_FLAG  21740             // 1
#define SMEM_FLOATS 21744
#define SMEM_BYTES (SMEM_FLOATS * 4)

__device__ float    g_max_atten[NJOB * QL];
__device__ float    g_score[NJOB];
__device__ unsigned g_done = 0;

__device__ __forceinline__ void fma_f32x2(unsigned long long& acc,
                                          unsigned long long a,
                                          unsigned long long b)
{
    asm("fma.rn.f32x2 %0, %1, %2, %0;" : "+l"(acc) : "l"(a), "l"(b));
}

__device__ __forceinline__ unsigned long long pack2(float v)
{
    unsigned long long r;
    uint32_t u = __float_as_uint(v);
    asm("mov.b64 %0, {%1, %1};" : "=l"(r) : "r"(u));
    return r;
}

__global__ void __launch_bounds__(512, 2)
topic_fused(const int* __restrict__ q, const int* __restrict__ alia,
            const float* __restrict__ els, const float* __restrict__ elo,
            const float* __restrict__ cate, const float* __restrict__ emb,
            const float* __restrict__ sim_w, const float* __restrict__ sim_b,
            const float* __restrict__ enc_w, const float* __restrict__ enc_b,
            const float* __restrict__ qlin_w, const float* __restrict__ qlin_b,
            const float* __restrict__ cls_w, const float* __restrict__ cls_b,
            float* __restrict__ out)
{
    extern __shared__ float sm[];
    float* w1      = sm + OFF_W;
    float* w2      = w1 + EE;
    float* w3      = w2 + EE;
    float* q_emb   = sm + OFF_QE;
    float* aw3     = sm + OFF_AW3;
    float* encT    = sm + OFF_ENCT;
    float* atten   = sm + OFF_ATT;
    float* attensm = sm + OFF_ATTS;
    float* qW2     = sm + OFF_QW2;
    float* qmaskS  = sm + OFF_QM;
    float* aW1     = sm + OFF_AW1;
    float* amaskS  = sm + OFF_AM;
    float* red     = sm + OFF_RED;

    const int tid  = threadIdx.x;
    const int lane = tid & 31;
    const int wid  = tid >> 5;
    const int job  = blockIdx.x;
    const int b    = job / TN;

    const float simb = sim_b[0];

    for (int i = tid; i < 3 * EE; i += 512) sm[OFF_W + i] = sim_w[i];
    __syncthreads();

    // ---- q rows: warp handles rows wid and wid+16 INTERLEAVED (MLP 20) ----
    {
        const int j0 = wid, j1 = wid + 16;
        int idx0 = q[b * QL + j0];
        int idx1 = q[b * QL + j1];
        float x0[10], x1[10];
        float ss0 = 0.f, ss1 = 0.f;
        #pragma unroll
        for (int i = 0; i < 10; i++) {
            int e = lane + 32 * i;
            float v0 = (e < EE) ? emb[(size_t)idx0 * EE + e] : 0.f;
            float v1 = (e < EE) ? emb[(size_t)idx1 * EE + e] : 0.f;
            x0[i] = v0; ss0 += v0 * v0;
            x1[i] = v1; ss1 += v1 * v1;
        }
        #pragma unroll
        for (int o = 16; o; o >>= 1) {
            ss0 += __shfl_xor_sync(0xffffffffu, ss0, o);
            ss1 += __shfl_xor_sync(0xffffffffu, ss1, o);
        }
        float scale0 = (idx0 == 0) ? 0.f : 1.f / fmaxf(sqrtf(ss0), 1e-12f);
        float scale1 = (idx1 == 0) ? 0.f : 1.f / fmaxf(sqrtf(ss1), 1e-12f);
        float dot0 = 0.f, dot1 = 0.f;
        #pragma unroll
        for (int i = 0; i < 10; i++) {
            int e = lane + 32 * i;
            float v0 = x0[i] * scale0;
            float v1 = x1[i] * scale1;
            if (e < EE) {
                q_emb[j0 * QP + e] = v0;
                q_emb[j1 * QP + e] = v1;
                float w = w2[e];
                dot0 += v0 * w;
                dot1 += v1 * w;
            } else if (e < QP) {
                q_emb[j0 * QP + e] = 0.f;   // pad [300,308) only
                q_emb[j1 * QP + e] = 0.f;
            }
        }
        #pragma unroll
        for (int o = 16; o; o >>= 1) {
            dot0 += __shfl_xor_sync(0xffffffffu, dot0, o);
            dot1 += __shfl_xor_sync(0xffffffffu, dot1, o);
        }
        if (lane == 0) {
            qW2[j0]    = dot0;
            qmaskS[j0] = (idx0 != 0) ? 1.f : 0.f;
            qW2[j1]    = dot1;
            qmaskS[j1] = (idx1 != 0) ? 1.f : 0.f;
        }
    }

    // ---- alias rows (warps 0..9): normalize, aw3, encT[300..599], aW1 ----
    if (wid < AL) {
        int a = wid;
        int idx = alia[job * AL + a];
        float x[10];
        float ss = 0.f;
        #pragma unroll
        for (int i = 0; i < 10; i++) {
            int e = lane + 32 * i;
            float v = (e < EE) ? emb[(size_t)idx * EE + e] : 0.f;
            x[i] = v;
            ss += v * v;
        }
        #pragma unroll
        for (int o = 16; o; o >>= 1) ss += __shfl_xor_sync(0xffffffffu, ss, o);
        float scale = (idx == 0) ? 0.f : 1.f / fmaxf(sqrtf(ss), 1e-12f);
        float dot = 0.f;
        #pragma unroll
        for (int i = 0; i < 10; i++) {
            int e = lane + 32 * i;
            float v = x[i] * scale;
            if (e < EE) {
                aw3[a * AP + e] = v * w3[e];
                encT[(300 + e) * RS + a] = v;
                dot += v * w1[e];
            } else if (e < AP) {
                aw3[a * AP + e] = 0.f;     // pad [300,304)
            }
        }
        #pragma unroll
        for (int o = 16; o; o >>= 1) dot += __shfl_xor_sync(0xffffffffu, dot, o);
        if (lane == 0) {
            aW1[a]    = dot;
            amaskS[a] = (idx != 0) ? 1.f : 0.f;
        }
    }
    __syncthreads();

    // ---- fused attention + softmax: warp = a, lane = q ----
    if (wid < AL) {
        int a = wid, qi = lane;
        const float4* qe = reinterpret_cast<const float4*>(q_emb + qi * QP);
        const float4* ar = reinterpret_cast<const float4*>(aw3 + a * AP);
        float d = 0.f;
        #pragma unroll 5
        for (int c = 0; c < 75; c++) {
            float4 qv = qe[c];
            float4 av = ar[c];
            d += av.x * qv.x + av.y * qv.y + av.z * qv.z + av.w * qv.w;
        }
        float val = aW1[a] + qW2[qi] + d + simb;
        float m = amaskS[a] * qmaskS[qi];
        val = m * val + (1.f - m) * NEGV;
        atten[a * QL + qi] = val;
        float mx = val;
        #pragma unroll
        for (int o = 16; o; o >>= 1) mx = fmaxf(mx, __shfl_xor_sync(0xffffffffu, mx, o));
        float ex = expf(val - mx);
        float s = ex;
        #pragma unroll
        for (int o = 16; o; o >>= 1) s += __shfl_xor_sync(0xffffffffu, s, o);
        attensm[a * QL + qi] = ex / s;
    }
    __syncthreads();

    // ---- cross-a max (warp 10) runs concurrently with alig ----
    if (wid == 10) {
        float mx = atten[lane];
        #pragma unroll
        for (int a = 1; a < AL; a++) mx = fmaxf(mx, atten[a * QL + lane]);
        g_max_atten[job * QL + lane] = mx;
    }

    // ---- alig -> encT rows 0..299 (float4 over e) ----
    for (int p = tid; p < AL * 75; p += 512) {
        int a = p / 75, c = p - a * 75;
        const float* as = attensm + a * QL;
        float4 acc = make_float4(0.f, 0.f, 0.f, 0.f);
        #pragma unroll
        for (int qi = 0; qi < QL; qi++) {
            float s = as[qi];
            float4 qv = *reinterpret_cast<const float4*>(q_emb + qi * QP + c * 4);
            acc.x += s * qv.x; acc.y += s * qv.y; acc.z += s * qv.z; acc.w += s * qv.w;
        }
        int e = c * 4;
        encT[(e + 0) * RS + a] = acc.x;
        encT[(e + 1) * RS + a] = acc.y;
        encT[(e + 2) * RS + a] = acc.z;
        encT[(e + 3) * RS + a] = acc.w;
    }
    __syncthreads();

    // ---- enc GEMM: 128 h-pairs x 4 e-quarters, batched weight prefetch (MLP 6) ----
    {
        const int pr  = tid & 127;         // h-pair index: h0=2p, h1=2p+1
        const int qtr = tid >> 7;          // e-quarter 0..3
        const int e0  = qtr * 150;
        const float2* W2 = reinterpret_cast<const float2*>(enc_w) + pr;

        unsigned long long A01 = 0ull, A23 = 0ull, A45 = 0ull, A67 = 0ull, A89 = 0ull;
        unsigned long long B01 = 0ull, B23 = 0ull, B45 = 0ull, B67 = 0ull, B89 = 0ull;

        #pragma unroll 1
        for (int eb = e0; eb < e0 + 150; eb += 6) {   // 150 = 25 * 6
            float2 wv[6];
            #pragma unroll
            for (int k = 0; k < 6; k++)
                wv[k] = __ldg(W2 + (size_t)(eb + k) * (HH / 2));

            #pragma unroll
            for (int k = 0; k < 6; k++) {
                unsigned long long wp0 = pack2(wv[k].x);
                unsigned long long wp1 = pack2(wv[k].y);

                const float* row = encT + (eb + k) * RS;
                ulonglong2 p0 = *reinterpret_cast<const ulonglong2*>(row);
                ulonglong2 p1 = *reinterpret_cast<const ulonglong2*>(row + 4);
                unsigned long long p2 =
                    *reinterpret_cast<const unsigned long long*>(row + 8);

                fma_f32x2(A01, p0.x, wp0);
                fma_f32x2(A23, p0.y, wp0);
                fma_f32x2(A45, p1.x, wp0);
                fma_f32x2(A67, p1.y, wp0);
                fma_f32x2(A89, p2,   wp0);

                fma_f32x2(B01, p0.x, wp1);
                fma_f32x2(B23, p0.y, wp1);
                fma_f32x2(B45, p1.x, wp1);
                fma_f32x2(B67, p1.y, wp1);
                fma_f32x2(B89, p2,   wp1);
            }
        }

        __syncthreads();   // q_emb region now dead -> reuse as partials
        unsigned long long* partial = reinterpret_cast<unsigned long long*>(q_emb);
        if (qtr != 0) {
            unsigned long long* dst = partial + ((size_t)(qtr - 1) * 128 + pr) * 10;
            dst[0] = A01; dst[1] = A23; dst[2] = A45; dst[3] = A67; dst[4] = A89;
            dst[5] = B01; dst[6] = B23; dst[7] = B45; dst[8] = B67; dst[9] = B89;
        }
        __syncthreads();

        if (qtr == 0) {                     // tid 0..127 = warps 0..3
            unsigned long long C[10] = {A01, A23, A45, A67, A89,
                                        B01, B23, B45, B67, B89};
            #pragma unroll
            for (int qq = 0; qq < 3; qq++) {
                const unsigned long long* src = partial + ((size_t)qq * 128 + pr) * 10;
                #pragma unroll
                for (int k = 0; k < 10; k++) {
                    unsigned long long v = src[k];
                    float lo = __uint_as_float((uint32_t)C[k]) + __uint_as_float((uint32_t)v);
                    float hi = __uint_as_float((uint32_t)(C[k] >> 32)) + __uint_as_float((uint32_t)(v >> 32));
                    C[k] = ((unsigned long long)__float_as_uint(hi) << 32) | __float_as_uint(lo);
                }
            }
            float2 eb = *reinterpret_cast<const float2*>(enc_b + 2 * pr);
            float2 qw = *reinterpret_cast<const float2*>(qlin_w + 2 * pr);
            float s0 = 0.f, s1 = 0.f;
            #pragma unroll
            for (int k = 0; k < 5; k++) {
                s0 += fmaxf(__uint_as_float((uint32_t)C[k]) + eb.x, 0.f);
                s0 += fmaxf(__uint_as_float((uint32_t)(C[k] >> 32)) + eb.x, 0.f);
                s1 += fmaxf(__uint_as_float((uint32_t)C[5 + k]) + eb.y, 0.f);
                s1 += fmaxf(__uint_as_float((uint32_t)(C[5 + k] >> 32)) + eb.y, 0.f);
            }
            float val = s0 * qw.x + s1 * qw.y;
            #pragma unroll
            for (int o = 16; o; o >>= 1) val += __shfl_xor_sync(0xffffffffu, val, o);
            if (lane == 0) red[wid] = val;
        }
        __syncthreads();
        if (tid == 0) {
            g_score[job] = red[0] + red[1] + red[2] + red[3];
        }
    }

    // ---- finisher-block pattern: last arriving block computes the finale ----
    __syncthreads();
    if (tid == 0) {
        __threadfence();
        unsigned old = atomicAdd(&g_done, 1u);
        sm[OFF_FLAG] = (old == NJOB - 1) ? 1.f : 0.f;
    }
    __syncthreads();
    if (sm[OFF_FLAG] != 0.f) {
        __threadfence();           // acquire: other blocks' g_score/g_max_atten visible
        if (tid == 0) g_done = 0;  // reset for next graph replay

        int fb = wid;              // warp per batch, 16 warps
        float c0w = cls_w[0], c1w = cls_w[1], c2w = cls_w[2],
              c3w = cls_w[3], c4w = cls_w[4];
        float cb = cls_b[0];
        float qb = qlin_b[0];

        float ml[TN];
        #pragma unroll
        for (int t = 0; t < TN; t++) {
            float eo = elo[fb * TN + t];
            float es = els[fb * TN + t];
            float ca = cate[(fb * TN + t) * 2 + 0];
            float cbv = cate[(fb * TN + t) * 2 + 1];
            float as = g_score[fb * TN + t] + qb;
            float lg = eo * c0w + es * c1w + ca * c2w + cbv * c3w + as * c4w + cb;
            float tm = ((es + eo) != 0.f) ? 1.f : 0.f;
            ml[t] = tm * lg + (1.f - tm) * NEGV;
        }
        if (lane < TN) out[fb * TN + lane] = ml[lane];

        float mx = ml[0];
        #pragma unroll
        for (int t = 1; t < TN; t++) mx = fmaxf(mx, ml[t]);
        float p[TN];
        float sum = 0.f;
        #pragma unroll
        for (int t = 0; t < TN; t++) { p[t] = expf(ml[t] - mx); sum += p[t]; }
        float inv = 1.f / sum;

        float s = 0.f;
        #pragma unroll
        for (int t = 0; t < TN; t++)
            s += p[t] * inv * g_max_atten[(fb * TN + t) * QL + lane];

        float m2 = s;
        #pragma unroll
        for (int o = 16; o; o >>= 1) m2 = fmaxf(m2, __shfl_xor_sync(0xffffffffu, m2, o));
        float ex = expf(s - m2);
        float tot = ex;
        #pragma unroll
        for (int o = 16; o; o >>= 1) tot += __shfl_xor_sync(0xffffffffu, tot, o);
        out[BB * TN + fb * QL + lane] = ex / tot;
    }
}

extern "C" void kernel_launch(void* const* d_in, const int* in_sizes, int n_in,
                              void* d_out, int out_size)
{
    const int*   q      = (const int*)  d_in[0];
    const int*   alia   = (const int*)  d_in[1];
    const float* els    = (const float*)d_in[2];
    const float* elo    = (const float*)d_in[3];
    const float* cate   = (const float*)d_in[4];
    const float* emb    = (const float*)d_in[5];
    const float* sim_w  = (const float*)d_in[6];
    const float* sim_b  = (const float*)d_in[7];
    const float* enc_w  = (const float*)d_in[8];
    const float* enc_b  = (const float*)d_in[9];
    const float* qlin_w = (const float*)d_in[10];
    const float* qlin_b = (const float*)d_in[11];
    const float* cls_w  = (const float*)d_in[12];
    const float* cls_b  = (const float*)d_in[13];
    float* out = (float*)d_out;

    cudaFuncSetAttribute(topic_fused, cudaFuncAttributeMaxDynamicSharedMemorySize, SMEM_BYTES);

    topic_fused<<<NJOB, 512, SMEM_BYTES>>>(q, alia, els, elo, cate, emb,
                                           sim_w, sim_b, enc_w, enc_b,
                                           qlin_w, qlin_b, cls_w, cls_b, out);
}